// round 4
// baseline (speedup 1.0000x reference)
#include <cuda_runtime.h>
#include <cstdint>

// RaySamples volume rendering, round 4: cp.async staged SMEM pipeline.
//
// The LDG-based versions all stalled at ~55-60% DRAM because load
// concurrency was tied to warp scoreboards (load phase / compute phase
// never overlap chip-wide). Here a 3-stage cp.async pipeline keeps
// ~128KB/SM of copies in flight continuously, independent of the
// scan/MUFU compute tail.
//
// Tile = 8 rays (8 x 128 fp32 = 4KB per input). CTA(256 thr) = 8 warps,
// one warp per ray per tile, 4 tiles per CTA, 2048 CTAs.
// Output: d_out[0:N*K] = weights, d_out[N*K:2N*K] = transmittance.

static constexpr int N_RAYS        = 65536;
static constexpr int F4_PER_RAY    = 32;      // K=128 / 4
static constexpr int RAYS_PER_TILE = 8;
static constexpr int TILE_F4       = RAYS_PER_TILE * F4_PER_RAY;  // 256 float4
static constexpr int STAGES        = 3;
static constexpr int THREADS       = 256;
static constexpr int CTAS          = 2048;
static constexpr int TILES_PER_CTA = N_RAYS / RAYS_PER_TILE / CTAS;  // 4

__device__ __forceinline__ void cp_async16(void* smem_dst, const void* gsrc) {
    uint32_t s = (uint32_t)__cvta_generic_to_shared(smem_dst);
    asm volatile("cp.async.cg.shared.global [%0], [%1], 16;\n" :: "r"(s), "l"(gsrc));
}
__device__ __forceinline__ void cp_commit() {
    asm volatile("cp.async.commit_group;\n" ::: "memory");
}
template <int N>
__device__ __forceinline__ void cp_wait() {
    asm volatile("cp.async.wait_group %0;\n" :: "n"(N) : "memory");
}

__global__ void __launch_bounds__(THREADS) ray_samples_kernel(
    const float4* __restrict__ dens,
    const float4* __restrict__ delt,
    float4* __restrict__ w_out,
    float4* __restrict__ t_out)
{
    __shared__ float4 buf[STAGES][2][TILE_F4];   // 3 * 2 * 256 * 16B = 24 KB

    const int tid  = threadIdx.x;
    const int lane = tid & 31;
    const int warp = tid >> 5;                   // 0..7 -> ray within tile
    const int tile0 = blockIdx.x * TILES_PER_CTA;

    // Each of the 256 threads copies exactly one float4 per input per stage.
    auto issue_tile = [&](int tile, int stage) {
        const int g = tile * TILE_F4 + tid;
        cp_async16(&buf[stage][0][tid], &dens[g]);
        cp_async16(&buf[stage][1][tid], &delt[g]);
        cp_commit();
    };

    // Prologue: fill STAGES-1 stages
    #pragma unroll
    for (int s = 0; s < STAGES - 1; ++s)
        issue_tile(tile0 + s, s);

    #pragma unroll
    for (int it = 0; it < TILES_PER_CTA; ++it) {
        // Wait until the oldest group (stage it%STAGES) has landed.
        cp_wait<STAGES - 2>();
        __syncthreads();

        const int stage = it % STAGES;

        // Refill the stage consumed at iteration it-1 (safe: everyone passed
        // the barrier above, so no warp still reads it). Always commit a
        // group so the wait_group accounting stays uniform.
        const int nt = it + STAGES - 1;
        if (nt < TILES_PER_CTA) {
            const int g = (tile0 + nt) * TILE_F4 + tid;
            const int ns = nt % STAGES;
            cp_async16(&buf[ns][0][tid], &dens[g]);
            cp_async16(&buf[ns][1][tid], &delt[g]);
        }
        cp_commit();

        // ---- compute: warp w handles ray (tile*8 + w), lane l -> float4 l ----
        const float4 d = buf[stage][0][warp * F4_PER_RAY + lane];
        const float4 l = buf[stage][1][warp * F4_PER_RAY + lane];

        const float dd0 = d.x * l.x;
        const float dd1 = d.y * l.y;
        const float dd2 = d.z * l.z;
        const float dd3 = d.w * l.w;
        const float local_sum = (dd0 + dd1) + (dd2 + dd3);

        // Inclusive warp scan of per-lane sums
        float scan = local_sum;
        #pragma unroll
        for (int off = 1; off < 32; off <<= 1) {
            float v = __shfl_up_sync(0xffffffffu, scan, off);
            if (lane >= off) scan += v;
        }
        const float excl = scan - local_sum;

        // 5 MUFU per 4 samples: T chain + W_i = T_i - T_i*e_i
        const float e0 = __expf(-dd0);
        const float e1 = __expf(-dd1);
        const float e2 = __expf(-dd2);
        const float e3 = __expf(-dd3);

        const float t0 = __expf(-excl);
        const float t1 = t0 * e0;
        const float t2 = t1 * e1;
        const float t3 = t2 * e2;

        const float4 T = make_float4(t0, t1, t2, t3);
        const float4 W = make_float4(t0 - t1,
                                     t1 - t2,
                                     t2 - t3,
                                     t3 - t3 * e3);

        const int gidx = (tile0 + it) * TILE_F4 + warp * F4_PER_RAY + lane;
        w_out[gidx] = W;
        t_out[gidx] = T;
    }
}

extern "C" void kernel_launch(void* const* d_in, const int* in_sizes, int n_in,
                              void* d_out, int out_size)
{
    const float4* dens = (const float4*)d_in[0];  // densities [N, K, 1] fp32
    const float4* delt = (const float4*)d_in[1];  // deltas    [N, K, 1] fp32
    float* out = (float*)d_out;

    const int total_elems = N_RAYS * 128;
    float4* w_out = (float4*)out;                 // weights
    float4* t_out = (float4*)(out + total_elems); // transmittance

    ray_samples_kernel<<<CTAS, THREADS>>>(dens, delt, w_out, t_out);
}

// round 13
// speedup vs baseline: 1.0979x; 1.0979x over previous
#include <cuda_runtime.h>
#include <cstdint>

// RaySamples volume rendering: L2-residency play (fixed encoding).
//
// Per-replay traffic: 64 MiB input reads + 64 MiB output writes. Inputs are
// re-read every graph replay; they fit in L2 (126 MB) but get evicted by the
// output writes. Pin inputs with an evict_last cache policy (createpolicy +
// ld.global.L2::cache_hint -- the only ptxas-legal form for v4.f32 on
// sm_103), and stream outputs with st.global.cs (evict-first). Steady-state
// DRAM then carries only the compulsory output writes.
//
// Compute structure = round-1 (best DRAM%): one warp per ray, one float4
// per lane, warp-shuffle exclusive scan, 5-MUFU epilogue.
// Output: d_out[0:N*K] = weights, d_out[N*K:2N*K] = transmittance.

static constexpr int N_RAYS    = 65536;
static constexpr int K_SAMPLES = 128;

__device__ __forceinline__ float4 ld_evict_last(const float4* p, uint64_t policy) {
    float4 v;
    asm volatile("ld.global.L2::cache_hint.v4.f32 {%0,%1,%2,%3}, [%4], %5;"
                 : "=f"(v.x), "=f"(v.y), "=f"(v.z), "=f"(v.w)
                 : "l"(p), "l"(policy));
    return v;
}

__device__ __forceinline__ void st_streaming(float4* p, float4 v) {
    asm volatile("st.global.cs.v4.f32 [%0], {%1,%2,%3,%4};"
                 :: "l"(p), "f"(v.x), "f"(v.y), "f"(v.z), "f"(v.w)
                 : "memory");
}

__global__ void __launch_bounds__(256) ray_samples_kernel(
    const float4* __restrict__ dens,
    const float4* __restrict__ delt,
    float4* __restrict__ w_out,
    float4* __restrict__ t_out)
{
    const int idx  = blockIdx.x * blockDim.x + threadIdx.x;
    const int lane = threadIdx.x & 31;

    // Fraction-1.0 evict_last policy for the input loads.
    uint64_t policy;
    asm volatile("createpolicy.fractional.L2::evict_last.b64 %0, 1.0;"
                 : "=l"(policy));

    const float4 d  = ld_evict_last(&dens[idx], policy);
    const float4 dl = ld_evict_last(&delt[idx], policy);

    const float dd0 = d.x * dl.x;
    const float dd1 = d.y * dl.y;
    const float dd2 = d.z * dl.z;
    const float dd3 = d.w * dl.w;

    const float local_sum = (dd0 + dd1) + (dd2 + dd3);

    // Inclusive warp scan of per-lane sums
    float scan = local_sum;
    #pragma unroll
    for (int off = 1; off < 32; off <<= 1) {
        float v = __shfl_up_sync(0xffffffffu, scan, off);
        if (lane >= off) scan += v;
    }
    const float excl = scan - local_sum;   // exclusive optical depth at sample 4*lane

    // 5 MUFU per 4 samples: e_i reused for T chain; W_i = T_i - T_{i+1}
    const float e0 = __expf(-dd0);
    const float e1 = __expf(-dd1);
    const float e2 = __expf(-dd2);
    const float e3 = __expf(-dd3);

    const float t0 = __expf(-excl);
    const float t1 = t0 * e0;
    const float t2 = t1 * e1;
    const float t3 = t2 * e2;

    const float4 T = make_float4(t0, t1, t2, t3);
    const float4 W = make_float4(t0 - t1,
                                 t1 - t2,
                                 t2 - t3,
                                 t3 - t3 * e3);

    st_streaming(&w_out[idx], W);
    st_streaming(&t_out[idx], T);
}

extern "C" void kernel_launch(void* const* d_in, const int* in_sizes, int n_in,
                              void* d_out, int out_size)
{
    const float4* dens = (const float4*)d_in[0];  // densities [N, K, 1] fp32
    const float4* delt = (const float4*)d_in[1];  // deltas    [N, K, 1] fp32
    float* out = (float*)d_out;

    const int total_elems = N_RAYS * K_SAMPLES;
    float4* w_out = (float4*)out;                 // weights
    float4* t_out = (float4*)(out + total_elems); // transmittance

    const int total_f4 = total_elems / 4;         // 2,097,152
    const int threads  = 256;
    const int blocks   = total_f4 / threads;      // 8192
    ray_samples_kernel<<<blocks, threads>>>(dens, delt, w_out, t_out);
}